// round 1
// baseline (speedup 1.0000x reference)
#include <cuda_runtime.h>

// Problem constants
#define B_   128
#define L_   512
#define D_   130            // E + 2
#define W_   256
#define KH_  5
#define CN_  4
#define G_   4
#define GC_  64             // W_/G_
#define Lp_  508            // L - KH + 1
#define NB_  65024          // B_*Lp_
#define K1_  650            // KH_*D_
#define LBL_ 53
#define EPSF 1e-5f
#define NEGF (-100000.0f)
#define FNEG (-3.0e38f)

// Scratch (static device memory -- no allocations allowed)
__device__ float  g_h[(size_t)B_ * L_ * D_];     // [b][l][d]
__device__ float  g_y[(size_t)W_ * NB_];         // [w][b*Lp+l]
__device__ float  g_z[(size_t)W_ * NB_];
__device__ float  g_xI[(size_t)W_ * NB_];
__device__ float2 g_stats[B_ * G_];              // (mean, rstd)
__device__ float  g_feat[B_ * 3 * W_];

// ---------------------------------------------------------------------------
// 1) embedding + position features -> g_h [B, L, 130]
// ---------------------------------------------------------------------------
__global__ void embed_kernel(const int* __restrict__ x,
                             const float* __restrict__ pe,
                             const float* __restrict__ emb)
{
    int bl = blockIdx.x;           // b*L + l
    int d  = threadIdx.x;          // 0..129
    float v;
    if (d < 128) {
        int tok = x[bl];
        v = emb[(size_t)tok * 128 + d];
    } else {
        v = pe[bl * 2 + (d - 128)];
    }
    g_h[(size_t)bl * D_ + d] = v;
}

// ---------------------------------------------------------------------------
// SGEMM tiling config
// ---------------------------------------------------------------------------
#define BM 128
#define BN 128
#define BK 16
#define TM 8
#define TN 8

// ---------------------------------------------------------------------------
// 2) conv1 as per-batch GEMM [256 x 650] @ [650 x 508], fused bias+BN+PReLU
//    writes g_y and g_xI
// ---------------------------------------------------------------------------
__global__ __launch_bounds__(256) void conv1_kernel(
    const float* __restrict__ A,       // conv1_w viewed [256][650]
    const float* __restrict__ bias,    // conv1_b [256]
    const float* __restrict__ bg, const float* __restrict__ bb,
    const float* __restrict__ bmu, const float* __restrict__ bvv,
    const float* __restrict__ pw)      // prelu1_w (scalar)
{
    __shared__ float As[BK][BM];
    __shared__ float Bs[BK][BN];
    int b  = blockIdx.z;
    const float* hb = g_h + (size_t)b * (L_ * D_);
    int n0 = blockIdx.x * BN;
    int m0 = blockIdx.y * BM;
    int t  = threadIdx.x;
    int arow = t >> 1, ac0 = (t & 1) * 8;   // A tile: (m=arow, k=ac0..ac0+7)
    int bn_  = t >> 1, bc0 = (t & 1) * 8;   // B tile: (n=bn_,  k=bc0..bc0+7)
    int tx = t & 15, ty = t >> 4;

    float acc[TM][TN];
    #pragma unroll
    for (int i = 0; i < TM; i++)
        #pragma unroll
        for (int j = 0; j < TN; j++) acc[i][j] = 0.f;

    for (int k0 = 0; k0 < K1_; k0 += BK) {
        #pragma unroll
        for (int i = 0; i < 8; i++) {
            int k = k0 + ac0 + i;
            As[ac0 + i][arow] = (k < K1_) ? A[(m0 + arow) * K1_ + k] : 0.f;
        }
        int n = n0 + bn_;
        #pragma unroll
        for (int i = 0; i < 8; i++) {
            int k = k0 + bc0 + i;
            Bs[bc0 + i][bn_] = (n < Lp_ && k < K1_) ? hb[n * D_ + k] : 0.f;
        }
        __syncthreads();
        #pragma unroll
        for (int k = 0; k < BK; k++) {
            float ra[TM], rb[TN];
            *(float4*)&ra[0] = *(const float4*)&As[k][ty * TM];
            *(float4*)&ra[4] = *(const float4*)&As[k][ty * TM + 4];
            *(float4*)&rb[0] = *(const float4*)&Bs[k][tx * TN];
            *(float4*)&rb[4] = *(const float4*)&Bs[k][tx * TN + 4];
            #pragma unroll
            for (int i = 0; i < TM; i++)
                #pragma unroll
                for (int j = 0; j < TN; j++)
                    acc[i][j] += ra[i] * rb[j];
        }
        __syncthreads();
    }

    float p = pw[0];
    #pragma unroll
    for (int i = 0; i < TM; i++) {
        int m = m0 + ty * TM + i;
        float scale = rsqrtf(bvv[m] + EPSF) * bg[m];
        float off   = bb[m] - bmu[m] * scale;
        float bi    = bias[m];
        #pragma unroll
        for (int j = 0; j < TN; j++) {
            int n = n0 + tx * TN + j;
            if (n < Lp_) {
                float v = (acc[i][j] + bi) * scale + off;
                v = v > 0.f ? v : p * v;
                size_t o = (size_t)m * NB_ + (size_t)b * Lp_ + n;
                g_y[o]  = v;
                g_xI[o] = v;
            }
        }
    }
}

// ---------------------------------------------------------------------------
// 3) conv-block GEMM: g_z[256 x 65024] = cb_w_i[256 x 256] @ g_y + cb_b_i
// ---------------------------------------------------------------------------
__global__ __launch_bounds__(256) void cbgemm_kernel(
    const float* __restrict__ A,      // cb_w + i*W*W
    const float* __restrict__ bias)   // cb_b + i*W
{
    __shared__ float As[BK][BM];
    __shared__ float Bs[BK][BN];
    int n0 = blockIdx.x * BN;
    int m0 = blockIdx.y * BM;
    int t  = threadIdx.x;
    int arow = t >> 1, ac0 = (t & 1) * 8;
    int brow = t >> 4, bc0 = (t & 15) * 8;
    int tx = t & 15, ty = t >> 4;

    float acc[TM][TN];
    #pragma unroll
    for (int i = 0; i < TM; i++)
        #pragma unroll
        for (int j = 0; j < TN; j++) acc[i][j] = 0.f;

    for (int k0 = 0; k0 < W_; k0 += BK) {
        const float* Ap = A + (m0 + arow) * W_ + k0 + ac0;
        #pragma unroll
        for (int i = 0; i < 8; i++) As[ac0 + i][arow] = Ap[i];
        const float* Bp = g_y + (size_t)(k0 + brow) * NB_ + n0 + bc0;
        *(float4*)&Bs[brow][bc0]     = *(const float4*)Bp;
        *(float4*)&Bs[brow][bc0 + 4] = *(const float4*)(Bp + 4);
        __syncthreads();
        #pragma unroll
        for (int k = 0; k < BK; k++) {
            float ra[TM], rb[TN];
            *(float4*)&ra[0] = *(const float4*)&As[k][ty * TM];
            *(float4*)&ra[4] = *(const float4*)&As[k][ty * TM + 4];
            *(float4*)&rb[0] = *(const float4*)&Bs[k][tx * TN];
            *(float4*)&rb[4] = *(const float4*)&Bs[k][tx * TN + 4];
            #pragma unroll
            for (int i = 0; i < TM; i++)
                #pragma unroll
                for (int j = 0; j < TN; j++)
                    acc[i][j] += ra[i] * rb[j];
        }
        __syncthreads();
    }

    #pragma unroll
    for (int i = 0; i < TM; i++) {
        int m = m0 + ty * TM + i;
        float bi = bias[m];
        #pragma unroll
        for (int j = 0; j < TN; j++) {
            g_z[(size_t)m * NB_ + n0 + tx * TN + j] = acc[i][j] + bi;
        }
    }
}

// ---------------------------------------------------------------------------
// 4) GroupNorm stats per (b, g): mean/var over 64 channels x 508 positions
// ---------------------------------------------------------------------------
__global__ void gnstats_kernel()
{
    __shared__ double ss[256];
    __shared__ double sq[256];
    int g = blockIdx.x, b = blockIdx.y, t = threadIdx.x;
    double s = 0.0, q = 0.0;
    for (int e = t; e < GC_ * Lp_; e += 256) {
        int c = e / Lp_, l = e - c * Lp_;
        float v = g_z[(size_t)(g * GC_ + c) * NB_ + (size_t)b * Lp_ + l];
        s += v;
        q += (double)v * v;
    }
    ss[t] = s; sq[t] = q;
    __syncthreads();
    for (int o = 128; o > 0; o >>= 1) {
        if (t < o) { ss[t] += ss[t + o]; sq[t] += sq[t + o]; }
        __syncthreads();
    }
    if (t == 0) {
        double cnt  = (double)(GC_ * Lp_);
        double mean = ss[0] / cnt;
        double var  = sq[0] / cnt - mean * mean;
        g_stats[b * G_ + g] = make_float2((float)mean, rsqrtf((float)var + EPSF));
    }
}

// ---------------------------------------------------------------------------
// 5) GroupNorm apply + PReLU + residual: g_y = prelu(norm(g_z)) + g_y
// ---------------------------------------------------------------------------
__global__ void gnapply_kernel(const float* __restrict__ gamma,
                               const float* __restrict__ beta,
                               const float* __restrict__ pp)
{
    unsigned idx = blockIdx.x * 256u + threadIdx.x;
    if (idx >= (unsigned)W_ * NB_) return;
    unsigned w = idx / NB_;
    unsigned r = idx - w * NB_;
    unsigned b = r / Lp_;
    float2 st = g_stats[b * G_ + (w >> 6)];
    float v = (g_z[idx] - st.x) * st.y * gamma[w] + beta[w];
    float p = pp[0];
    v = v > 0.f ? v : p * v;
    g_y[idx] += v;
}

// ---------------------------------------------------------------------------
// 6) final residual + masked segment max -> g_feat [B, 3*W]
//    one warp per (b, w)
// ---------------------------------------------------------------------------
__global__ void maxfeat_kernel(const int* __restrict__ posE)
{
    int gw   = (blockIdx.x * blockDim.x + threadIdx.x) >> 5;
    int lane = threadIdx.x & 31;
    if (gw >= B_ * W_) return;
    int b = gw >> 8;           // / W_
    int w = gw & 255;
    int p0 = posE[b * 2] + 1;
    int p1 = posE[b * 2 + 1] + 1;
    const float* yr = g_y  + (size_t)w * NB_ + (size_t)b * Lp_;
    const float* xr = g_xI + (size_t)w * NB_ + (size_t)b * Lp_;
    float m1 = FNEG, m2 = FNEG, m3 = FNEG;
    for (int l = lane; l < Lp_; l += 32) {
        float v = yr[l] + xr[l];
        float a1 = v + ((l >= p0) ? NEGF : 0.f);
        float a2 = v + ((l < p0 || l >= p1) ? NEGF : 0.f);
        float a3 = v + ((l < p1) ? NEGF : 0.f);
        m1 = fmaxf(m1, a1);
        m2 = fmaxf(m2, a2);
        m3 = fmaxf(m3, a3);
    }
    #pragma unroll
    for (int o = 16; o > 0; o >>= 1) {
        m1 = fmaxf(m1, __shfl_down_sync(0xffffffffu, m1, o));
        m2 = fmaxf(m2, __shfl_down_sync(0xffffffffu, m2, o));
        m3 = fmaxf(m3, __shfl_down_sync(0xffffffffu, m3, o));
    }
    if (lane == 0) {
        g_feat[b * 3 * W_ + 0 * W_ + w] = m1;
        g_feat[b * 3 * W_ + 1 * W_ + w] = m2;
        g_feat[b * 3 * W_ + 2 * W_ + w] = m3;
    }
}

// ---------------------------------------------------------------------------
// 7) dense head + softmax. One block (256 threads) per batch element.
// ---------------------------------------------------------------------------
__global__ void dense_kernel(
    const float* __restrict__ d0w, const float* __restrict__ d0b,
    const float* __restrict__ d1w, const float* __restrict__ d1b,
    const float* __restrict__ bndg, const float* __restrict__ bndb,
    const float* __restrict__ bndm, const float* __restrict__ bndv,
    const float* __restrict__ pd,
    const float* __restrict__ finw, const float* __restrict__ finb,
    float* __restrict__ out)
{
    __shared__ float sf[3 * W_];
    __shared__ float sh[W_];
    __shared__ float sl[LBL_];
    __shared__ float red[2];
    int b = blockIdx.x, t = threadIdx.x;

    for (int i = t; i < 3 * W_; i += 256) sf[i] = g_feat[b * 3 * W_ + i];
    __syncthreads();

    // layer 0: 768 -> 256, BN row 0, PReLU
    float acc = d0b[t];
    {
        const float* wr = d0w + t * (3 * W_);
        #pragma unroll 8
        for (int k = 0; k < 3 * W_; k++) acc += sf[k] * wr[k];
    }
    acc = (acc - bndm[t]) * rsqrtf(bndv[t] + EPSF) * bndg[t] + bndb[t];
    {
        float p = pd[0];
        acc = acc > 0.f ? acc : p * acc;
    }
    sh[t] = acc;
    __syncthreads();

    // layer 1: 256 -> 256, BN row 1, PReLU
    float a2 = d1b[t];
    {
        const float* wr = d1w + t * W_;
        #pragma unroll 8
        for (int k = 0; k < W_; k++) a2 += sh[k] * wr[k];
    }
    a2 = (a2 - bndm[W_ + t]) * rsqrtf(bndv[W_ + t] + EPSF) * bndg[W_ + t] + bndb[W_ + t];
    {
        float p = pd[1];
        a2 = a2 > 0.f ? a2 : p * a2;
    }
    __syncthreads();
    sh[t] = a2;
    __syncthreads();

    // final: 256 -> 53
    if (t < LBL_) {
        float a3 = finb[t];
        const float* wr = finw + t * W_;
        #pragma unroll 8
        for (int k = 0; k < W_; k++) a3 += sh[k] * wr[k];
        sl[t] = a3;
    }
    __syncthreads();
    if (t == 0) {
        float mx = FNEG;
        for (int i = 0; i < LBL_; i++) mx = fmaxf(mx, sl[i]);
        float s = 0.f;
        for (int i = 0; i < LBL_; i++) s += expf(sl[i] - mx);
        red[0] = mx;
        red[1] = 1.f / s;
    }
    __syncthreads();
    if (t < LBL_) out[b * LBL_ + t] = expf(sl[t] - red[0]) * red[1];
}

// ---------------------------------------------------------------------------
// launch
// ---------------------------------------------------------------------------
extern "C" void kernel_launch(void* const* d_in, const int* in_sizes, int n_in,
                              void* d_out, int out_size)
{
    const int*   x      = (const int*)d_in[0];
    const int*   posE   = (const int*)d_in[1];
    const float* pe     = (const float*)d_in[2];
    const float* emb    = (const float*)d_in[3];
    const float* c1w    = (const float*)d_in[4];
    const float* c1b    = (const float*)d_in[5];
    const float* bn1g   = (const float*)d_in[6];
    const float* bn1b   = (const float*)d_in[7];
    const float* bn1m   = (const float*)d_in[8];
    const float* bn1v   = (const float*)d_in[9];
    const float* p1w    = (const float*)d_in[10];
    const float* cbw    = (const float*)d_in[11];
    const float* cbb    = (const float*)d_in[12];
    const float* gng    = (const float*)d_in[13];
    const float* gnb    = (const float*)d_in[14];
    const float* cbp    = (const float*)d_in[15];
    const float* d0w    = (const float*)d_in[16];
    const float* d0b    = (const float*)d_in[17];
    const float* d1w    = (const float*)d_in[18];
    const float* d1b    = (const float*)d_in[19];
    const float* bndg   = (const float*)d_in[20];
    const float* bndb   = (const float*)d_in[21];
    const float* bndm   = (const float*)d_in[22];
    const float* bndv   = (const float*)d_in[23];
    const float* pd     = (const float*)d_in[24];
    const float* finw   = (const float*)d_in[25];
    const float* finb   = (const float*)d_in[26];
    float* out = (float*)d_out;

    // 1) embedding gather
    embed_kernel<<<B_ * L_, D_>>>(x, pe, emb);

    // 2) conv1 (GEMM per batch) fused bias+BN+PReLU -> g_y, g_xI
    {
        dim3 grid((Lp_ + BN - 1) / BN, W_ / BM, B_);   // (4, 2, 128)
        conv1_kernel<<<grid, 256>>>(c1w, c1b, bn1g, bn1b, bn1m, bn1v, p1w);
    }

    // 3) residual conv blocks
    for (int i = 0; i < CN_; i++) {
        dim3 gridg(NB_ / BN, W_ / BM);                 // (508, 2)
        cbgemm_kernel<<<gridg, 256>>>(cbw + (size_t)i * W_ * W_, cbb + i * W_);
        dim3 grids(G_, B_);
        gnstats_kernel<<<grids, 256>>>();
        unsigned total = (unsigned)W_ * NB_;
        gnapply_kernel<<<(total + 255) / 256, 256>>>(gng + i * W_, gnb + i * W_, cbp + i);
    }

    // 4) final residual + masked segment max
    {
        int warps = B_ * W_;                            // 32768 warps
        int threads = warps * 32;
        maxfeat_kernel<<<(threads + 255) / 256, 256>>>(posE);
    }

    // 5) dense head + softmax
    dense_kernel<<<B_, 256>>>(d0w, d0b, d1w, d1b, bndg, bndb, bndm, bndv,
                              pd, finw, finb, out);

    (void)in_sizes; (void)n_in; (void)out_size;
}

// round 2
// speedup vs baseline: 2.0920x; 2.0920x over previous
#include <cuda_runtime.h>
#include <cstdint>

// Problem constants
#define B_   128
#define L_   512
#define D_   130            // E + 2
#define W_   256
#define KH_  5
#define CN_  4
#define G_   4
#define GC_  64             // W_/G_
#define Lp_  508            // L - KH + 1
#define NB_  65024          // B_*Lp_
#define K1_  650            // KH_*D_
#define LBL_ 53
#define EPSF 1e-5f
#define NEGF (-100000.0f)
#define FNEG (-3.0e38f)

// Scratch (static device memory -- no allocations allowed)
__device__ float  g_h[(size_t)B_ * L_ * D_ + 16]; // [b][l][d]
__device__ float  g_y[(size_t)W_ * NB_];          // [w][b*Lp+l]
__device__ float  g_z[(size_t)W_ * NB_];
__device__ float  g_xI[(size_t)W_ * NB_];
__device__ float2 g_stats[B_ * G_];               // (mean, rstd)
__device__ float  g_feat[B_ * 3 * W_];

// ---------------------------------------------------------------------------
// helpers
// ---------------------------------------------------------------------------
__device__ __forceinline__ uint32_t f2t(float x) {
    uint32_t u;
    asm("cvt.rna.tf32.f32 %0, %1;" : "=r"(u) : "f"(x));
    return u;
}

__device__ __forceinline__ void mma8(float* c, const uint32_t* a, const uint32_t* b) {
    asm volatile(
        "mma.sync.aligned.m16n8k8.row.col.f32.tf32.tf32.f32 "
        "{%0,%1,%2,%3}, {%4,%5,%6,%7}, {%8,%9}, {%0,%1,%2,%3};"
        : "+f"(c[0]), "+f"(c[1]), "+f"(c[2]), "+f"(c[3])
        : "r"(a[0]), "r"(a[1]), "r"(a[2]), "r"(a[3]), "r"(b[0]), "r"(b[1]));
}

// ---------------------------------------------------------------------------
// 1) embedding + position features -> g_h [B, L, 130]
// ---------------------------------------------------------------------------
__global__ void embed_kernel(const int* __restrict__ x,
                             const float* __restrict__ pe,
                             const float* __restrict__ emb)
{
    int bl = blockIdx.x;           // b*L + l
    int d  = threadIdx.x;          // 0..129
    float v;
    if (d < 128) {
        int tok = x[bl];
        v = emb[(size_t)tok * 128 + d];
    } else {
        v = pe[bl * 2 + (d - 128)];
    }
    g_h[(size_t)bl * D_ + d] = v;
}

// ---------------------------------------------------------------------------
// 2) conv1 as per-batch tensor-core GEMM [256 x 650] @ [650 x 508]
//    C = A @ B, A row-major [m][k], B column (b,l) is contiguous k-slice of h.
//    Fused bias + BN + PReLU. Writes g_y and g_xI.
//    Block tile 128x128, BK=32, 8 warps (2x4), warp tile 64x32.
// ---------------------------------------------------------------------------
__global__ __launch_bounds__(256) void conv1_tc(
    const float* __restrict__ A, const float* __restrict__ bias,
    const float* __restrict__ bg, const float* __restrict__ bb,
    const float* __restrict__ bmu, const float* __restrict__ bvv,
    const float* __restrict__ pw)
{
    __shared__ uint32_t As[128][36];   // [m][k] tf32
    __shared__ uint32_t Bs[128][36];   // [n][k] tf32 (B naturally n-major)
    int b  = blockIdx.z;
    const float* hb = g_h + (size_t)b * (L_ * D_);
    int n0 = blockIdx.x * 128;
    int m0 = blockIdx.y * 128;
    int t = threadIdx.x, lane = t & 31, wid = t >> 5;
    int wm = wid >> 2, wn = wid & 3;
    int fr = lane >> 2, fc = lane & 3;

    float acc[4][4][4];
    #pragma unroll
    for (int i = 0; i < 4; i++)
        #pragma unroll
        for (int j = 0; j < 4; j++)
            #pragma unroll
            for (int q = 0; q < 4; q++) acc[i][j][q] = 0.f;

    int arow = t >> 1, akg = (t & 1) * 16;  // A tile loader
    int brow = t >> 1, bkg = (t & 1) * 16;  // B tile loader
    int nglob = n0 + brow;
    bool nok = nglob < Lp_;
    const float* arp = A + (size_t)(m0 + arow) * K1_;
    const float* brp = hb + (size_t)nglob * D_;

    for (int k0 = 0; k0 < K1_; k0 += 32) {
        // A tile: 8 float2 per thread (row stride 650 -> only 8B aligned)
        #pragma unroll
        for (int q = 0; q < 8; q++) {
            int k = k0 + akg + 2 * q;
            float2 v = make_float2(0.f, 0.f);
            if (k < K1_) v = *(const float2*)(arp + k);
            As[arow][akg + 2 * q]     = f2t(v.x);
            As[arow][akg + 2 * q + 1] = f2t(v.y);
        }
        // B tile: column (n) is contiguous 650-float window hb + n*130
        #pragma unroll
        for (int q = 0; q < 8; q++) {
            int k = k0 + bkg + 2 * q;
            float2 v = make_float2(0.f, 0.f);
            if (nok && k < K1_) v = *(const float2*)(brp + k);
            Bs[brow][bkg + 2 * q]     = f2t(v.x);
            Bs[brow][bkg + 2 * q + 1] = f2t(v.y);
        }
        __syncthreads();
        #pragma unroll
        for (int kk = 0; kk < 32; kk += 8) {
            uint32_t af[4][4], bf[4][2];
            #pragma unroll
            for (int i = 0; i < 4; i++) {
                int m = wm * 64 + 16 * i + fr;
                af[i][0] = As[m][kk + fc];
                af[i][1] = As[m + 8][kk + fc];
                af[i][2] = As[m][kk + fc + 4];
                af[i][3] = As[m + 8][kk + fc + 4];
            }
            #pragma unroll
            for (int j = 0; j < 4; j++) {
                int n = wn * 32 + 8 * j + fr;
                bf[j][0] = Bs[n][kk + fc];
                bf[j][1] = Bs[n][kk + fc + 4];
            }
            #pragma unroll
            for (int i = 0; i < 4; i++)
                #pragma unroll
                for (int j = 0; j < 4; j++)
                    mma8(acc[i][j], af[i], bf[j]);
        }
        __syncthreads();
    }

    // epilogue: bias + BN + PReLU, store g_y and g_xI
    float p = pw[0];
    #pragma unroll
    for (int i = 0; i < 4; i++) {
        int r0 = m0 + wm * 64 + 16 * i + fr;
        int r1 = r0 + 8;
        float s0 = rsqrtf(bvv[r0] + EPSF) * bg[r0];
        float o0 = bb[r0] - bmu[r0] * s0;
        float bi0 = bias[r0];
        float s1 = rsqrtf(bvv[r1] + EPSF) * bg[r1];
        float o1 = bb[r1] - bmu[r1] * s1;
        float bi1 = bias[r1];
        #pragma unroll
        for (int j = 0; j < 4; j++) {
            int c = n0 + wn * 32 + 8 * j + 2 * fc;
            if (c < Lp_) {
                float v0 = (acc[i][j][0] + bi0) * s0 + o0;
                float v1 = (acc[i][j][1] + bi0) * s0 + o0;
                float v2 = (acc[i][j][2] + bi1) * s1 + o1;
                float v3 = (acc[i][j][3] + bi1) * s1 + o1;
                v0 = v0 > 0.f ? v0 : p * v0;
                v1 = v1 > 0.f ? v1 : p * v1;
                v2 = v2 > 0.f ? v2 : p * v2;
                v3 = v3 > 0.f ? v3 : p * v3;
                size_t o_a = (size_t)r0 * NB_ + (size_t)b * Lp_ + c;
                size_t o_b = (size_t)r1 * NB_ + (size_t)b * Lp_ + c;
                *(float2*)(g_y  + o_a) = make_float2(v0, v1);
                *(float2*)(g_xI + o_a) = make_float2(v0, v1);
                *(float2*)(g_y  + o_b) = make_float2(v2, v3);
                *(float2*)(g_xI + o_b) = make_float2(v2, v3);
            }
        }
    }
}

// ---------------------------------------------------------------------------
// 3) conv-block tensor-core GEMM: g_z = cb_w_i[256x256] @ g_y[256x65024] + b
// ---------------------------------------------------------------------------
__global__ __launch_bounds__(256) void cb_tc(
    const float* __restrict__ A, const float* __restrict__ bias)
{
    __shared__ uint32_t As[128][36];    // [m][k]
    __shared__ uint32_t Bs[32][132];    // [k][n]
    int n0 = blockIdx.x * 128;
    int m0 = blockIdx.y * 128;
    int t = threadIdx.x, lane = t & 31, wid = t >> 5;
    int wm = wid >> 2, wn = wid & 3;
    int fr = lane >> 2, fc = lane & 3;

    float acc[4][4][4];
    #pragma unroll
    for (int i = 0; i < 4; i++)
        #pragma unroll
        for (int j = 0; j < 4; j++)
            #pragma unroll
            for (int q = 0; q < 4; q++) acc[i][j][q] = 0.f;

    int arow = t >> 1, akg = (t & 1) * 16;
    int bk = t >> 3, bng = (t & 7) * 16;
    const float* arp = A + (size_t)(m0 + arow) * W_;

    for (int k0 = 0; k0 < W_; k0 += 32) {
        #pragma unroll
        for (int q = 0; q < 4; q++) {
            float4 v = *(const float4*)(arp + k0 + akg + 4 * q);
            As[arow][akg + 4 * q]     = f2t(v.x);
            As[arow][akg + 4 * q + 1] = f2t(v.y);
            As[arow][akg + 4 * q + 2] = f2t(v.z);
            As[arow][akg + 4 * q + 3] = f2t(v.w);
        }
        const float* brp = g_y + (size_t)(k0 + bk) * NB_ + n0 + bng;
        #pragma unroll
        for (int q = 0; q < 4; q++) {
            float4 v = *(const float4*)(brp + 4 * q);
            uint4 u;
            u.x = f2t(v.x); u.y = f2t(v.y); u.z = f2t(v.z); u.w = f2t(v.w);
            *(uint4*)&Bs[bk][bng + 4 * q] = u;
        }
        __syncthreads();
        #pragma unroll
        for (int kk = 0; kk < 32; kk += 8) {
            uint32_t af[4][4], bf[4][2];
            #pragma unroll
            for (int i = 0; i < 4; i++) {
                int m = wm * 64 + 16 * i + fr;
                af[i][0] = As[m][kk + fc];
                af[i][1] = As[m + 8][kk + fc];
                af[i][2] = As[m][kk + fc + 4];
                af[i][3] = As[m + 8][kk + fc + 4];
            }
            #pragma unroll
            for (int j = 0; j < 4; j++) {
                int n = wn * 32 + 8 * j + fr;
                bf[j][0] = Bs[kk + fc][n];
                bf[j][1] = Bs[kk + fc + 4][n];
            }
            #pragma unroll
            for (int i = 0; i < 4; i++)
                #pragma unroll
                for (int j = 0; j < 4; j++)
                    mma8(acc[i][j], af[i], bf[j]);
        }
        __syncthreads();
    }

    #pragma unroll
    for (int i = 0; i < 4; i++) {
        int r0 = m0 + wm * 64 + 16 * i + fr;
        int r1 = r0 + 8;
        float bi0 = bias[r0], bi1 = bias[r1];
        #pragma unroll
        for (int j = 0; j < 4; j++) {
            int c = n0 + wn * 32 + 8 * j + 2 * fc;
            *(float2*)(g_z + (size_t)r0 * NB_ + c) =
                make_float2(acc[i][j][0] + bi0, acc[i][j][1] + bi0);
            *(float2*)(g_z + (size_t)r1 * NB_ + c) =
                make_float2(acc[i][j][2] + bi1, acc[i][j][3] + bi1);
        }
    }
}

// ---------------------------------------------------------------------------
// 4) GroupNorm stats per (b, g): fp32, vectorized. 508 = 127 float4 exactly.
// ---------------------------------------------------------------------------
__global__ void gnstats_kernel()
{
    __shared__ float ss[256];
    __shared__ float sq[256];
    int g = blockIdx.x, b = blockIdx.y, t = threadIdx.x;
    int c = t >> 2;          // channel within group (0..63)
    int q0 = t & 3;
    const float4* row = (const float4*)(g_z + (size_t)(g * GC_ + c) * NB_ + (size_t)b * Lp_);
    float s = 0.f, q = 0.f;
    for (int i = q0; i < 127; i += 4) {
        float4 v = row[i];
        s += v.x + v.y + v.z + v.w;
        q += v.x * v.x + v.y * v.y + v.z * v.z + v.w * v.w;
    }
    ss[t] = s; sq[t] = q;
    __syncthreads();
    for (int o = 128; o > 0; o >>= 1) {
        if (t < o) { ss[t] += ss[t + o]; sq[t] += sq[t + o]; }
        __syncthreads();
    }
    if (t == 0) {
        float cnt  = (float)(GC_ * Lp_);
        float mean = ss[0] / cnt;
        float var  = sq[0] / cnt - mean * mean;
        g_stats[b * G_ + g] = make_float2(mean, rsqrtf(var + EPSF));
    }
}

// ---------------------------------------------------------------------------
// 5) GroupNorm apply + PReLU + residual: g_y = prelu(norm(g_z)) + g_y
// ---------------------------------------------------------------------------
__global__ void gnapply_kernel(const float* __restrict__ gamma,
                               const float* __restrict__ beta,
                               const float* __restrict__ pp)
{
    unsigned idx = blockIdx.x * 256u + threadIdx.x;
    if (idx >= (unsigned)W_ * NB_) return;
    unsigned w = idx / NB_;
    unsigned r = idx - w * NB_;
    unsigned b = r / Lp_;
    float2 st = g_stats[b * G_ + (w >> 6)];
    float v = (g_z[idx] - st.x) * st.y * gamma[w] + beta[w];
    float p = pp[0];
    v = v > 0.f ? v : p * v;
    g_y[idx] += v;
}

// ---------------------------------------------------------------------------
// 6) final residual + masked segment max -> g_feat [B, 3*W]
// ---------------------------------------------------------------------------
__global__ void maxfeat_kernel(const int* __restrict__ posE)
{
    int gw   = (blockIdx.x * blockDim.x + threadIdx.x) >> 5;
    int lane = threadIdx.x & 31;
    if (gw >= B_ * W_) return;
    int b = gw >> 8;
    int w = gw & 255;
    int p0 = posE[b * 2] + 1;
    int p1 = posE[b * 2 + 1] + 1;
    const float* yr = g_y  + (size_t)w * NB_ + (size_t)b * Lp_;
    const float* xr = g_xI + (size_t)w * NB_ + (size_t)b * Lp_;
    float m1 = FNEG, m2 = FNEG, m3 = FNEG;
    for (int l = lane; l < Lp_; l += 32) {
        float v = yr[l] + xr[l];
        float a1 = v + ((l >= p0) ? NEGF : 0.f);
        float a2 = v + ((l < p0 || l >= p1) ? NEGF : 0.f);
        float a3 = v + ((l < p1) ? NEGF : 0.f);
        m1 = fmaxf(m1, a1);
        m2 = fmaxf(m2, a2);
        m3 = fmaxf(m3, a3);
    }
    #pragma unroll
    for (int o = 16; o > 0; o >>= 1) {
        m1 = fmaxf(m1, __shfl_down_sync(0xffffffffu, m1, o));
        m2 = fmaxf(m2, __shfl_down_sync(0xffffffffu, m2, o));
        m3 = fmaxf(m3, __shfl_down_sync(0xffffffffu, m3, o));
    }
    if (lane == 0) {
        g_feat[b * 3 * W_ + 0 * W_ + w] = m1;
        g_feat[b * 3 * W_ + 1 * W_ + w] = m2;
        g_feat[b * 3 * W_ + 2 * W_ + w] = m3;
    }
}

// ---------------------------------------------------------------------------
// 7) dense head + softmax. One block (256 threads) per batch element.
// ---------------------------------------------------------------------------
__global__ void dense_kernel(
    const float* __restrict__ d0w, const float* __restrict__ d0b,
    const float* __restrict__ d1w, const float* __restrict__ d1b,
    const float* __restrict__ bndg, const float* __restrict__ bndb,
    const float* __restrict__ bndm, const float* __restrict__ bndv,
    const float* __restrict__ pd,
    const float* __restrict__ finw, const float* __restrict__ finb,
    float* __restrict__ out)
{
    __shared__ float sf[3 * W_];
    __shared__ float sh[W_];
    __shared__ float sl[LBL_];
    __shared__ float red[2];
    int b = blockIdx.x, t = threadIdx.x;

    for (int i = t; i < 3 * W_; i += 256) sf[i] = g_feat[b * 3 * W_ + i];
    __syncthreads();

    float acc = d0b[t];
    {
        const float* wr = d0w + t * (3 * W_);
        #pragma unroll 8
        for (int k = 0; k < 3 * W_; k++) acc += sf[k] * wr[k];
    }
    acc = (acc - bndm[t]) * rsqrtf(bndv[t] + EPSF) * bndg[t] + bndb[t];
    { float p = pd[0]; acc = acc > 0.f ? acc : p * acc; }
    sh[t] = acc;
    __syncthreads();

    float a2 = d1b[t];
    {
        const float* wr = d1w + t * W_;
        #pragma unroll 8
        for (int k = 0; k < W_; k++) a2 += sh[k] * wr[k];
    }
    a2 = (a2 - bndm[W_ + t]) * rsqrtf(bndv[W_ + t] + EPSF) * bndg[W_ + t] + bndb[W_ + t];
    { float p = pd[1]; a2 = a2 > 0.f ? a2 : p * a2; }
    __syncthreads();
    sh[t] = a2;
    __syncthreads();

    if (t < LBL_) {
        float a3 = finb[t];
        const float* wr = finw + t * W_;
        #pragma unroll 8
        for (int k = 0; k < W_; k++) a3 += sh[k] * wr[k];
        sl[t] = a3;
    }
    __syncthreads();
    if (t == 0) {
        float mx = FNEG;
        for (int i = 0; i < LBL_; i++) mx = fmaxf(mx, sl[i]);
        float s = 0.f;
        for (int i = 0; i < LBL_; i++) s += expf(sl[i] - mx);
        red[0] = mx;
        red[1] = 1.f / s;
    }
    __syncthreads();
    if (t < LBL_) out[b * LBL_ + t] = expf(sl[t] - red[0]) * red[1];
}

// ---------------------------------------------------------------------------
// launch
// ---------------------------------------------------------------------------
extern "C" void kernel_launch(void* const* d_in, const int* in_sizes, int n_in,
                              void* d_out, int out_size)
{
    const int*   x      = (const int*)d_in[0];
    const int*   posE   = (const int*)d_in[1];
    const float* pe     = (const float*)d_in[2];
    const float* emb    = (const float*)d_in[3];
    const float* c1w    = (const float*)d_in[4];
    const float* c1b    = (const float*)d_in[5];
    const float* bn1g   = (const float*)d_in[6];
    const float* bn1b   = (const float*)d_in[7];
    const float* bn1m   = (const float*)d_in[8];
    const float* bn1v   = (const float*)d_in[9];
    const float* p1w    = (const float*)d_in[10];
    const float* cbw    = (const float*)d_in[11];
    const float* cbb    = (const float*)d_in[12];
    const float* gng    = (const float*)d_in[13];
    const float* gnb    = (const float*)d_in[14];
    const float* cbp    = (const float*)d_in[15];
    const float* d0w    = (const float*)d_in[16];
    const float* d0b    = (const float*)d_in[17];
    const float* d1w    = (const float*)d_in[18];
    const float* d1b    = (const float*)d_in[19];
    const float* bndg   = (const float*)d_in[20];
    const float* bndb   = (const float*)d_in[21];
    const float* bndm   = (const float*)d_in[22];
    const float* bndv   = (const float*)d_in[23];
    const float* pd     = (const float*)d_in[24];
    const float* finw   = (const float*)d_in[25];
    const float* finb   = (const float*)d_in[26];
    float* out = (float*)d_out;

    embed_kernel<<<B_ * L_, D_>>>(x, pe, emb);

    {
        dim3 grid((Lp_ + 127) / 128, W_ / 128, B_);   // (4, 2, 128)
        conv1_tc<<<grid, 256>>>(c1w, c1b, bn1g, bn1b, bn1m, bn1v, p1w);
    }

    for (int i = 0; i < CN_; i++) {
        dim3 gridg(NB_ / 128, W_ / 128);              // (508, 2)
        cb_tc<<<gridg, 256>>>(cbw + (size_t)i * W_ * W_, cbb + i * W_);
        dim3 grids(G_, B_);
        gnstats_kernel<<<grids, 256>>>();
        unsigned total = (unsigned)W_ * NB_;
        gnapply_kernel<<<(total + 255) / 256, 256>>>(gng + i * W_, gnb + i * W_, cbp + i);
    }

    {
        int warps = B_ * W_;
        int threads = warps * 32;
        maxfeat_kernel<<<(threads + 255) / 256, 256>>>(posE);
    }

    dense_kernel<<<B_, 256>>>(d0w, d0b, d1w, d1b, bndg, bndb, bndm, bndv,
                              pd, finw, finb, out);

    (void)in_sizes; (void)n_in; (void)out_size;
}

// round 3
// speedup vs baseline: 2.5896x; 1.2379x over previous
#include <cuda_runtime.h>
#include <cstdint>

// Problem constants
#define B_   128
#define L_   512
#define D_   130            // E + 2
#define W_   256
#define KH_  5
#define CN_  4
#define G_   4
#define GC_  64             // W_/G_
#define Lp_  508            // L - KH + 1
#define NB_  65024          // B_*Lp_
#define K1_  650            // KH_*D_
#define K1P_ 672            // padded K for conv1 (21 * 32)
#define LBL_ 53
#define EPSF 1e-5f
#define NEGF (-100000.0f)
#define FNEG (-3.0e38f)

// Scratch (static device memory -- no allocations allowed)
__device__ float  g_h[(size_t)B_ * L_ * D_ + 1024]; // [b][l][d] + OOB pad
__device__ float  g_w1[(size_t)W_ * K1P_];          // conv1 weights, K padded w/ zeros
__device__ float  g_y[(size_t)W_ * NB_];            // [w][b*Lp+l]
__device__ float  g_z[(size_t)W_ * NB_];
__device__ float  g_xI[(size_t)W_ * NB_];
__device__ float2 g_stats[B_ * G_];                 // (mean, rstd)
__device__ float  g_feat[B_ * 3 * W_];

// ---------------------------------------------------------------------------
// helpers
// ---------------------------------------------------------------------------
__device__ __forceinline__ uint32_t cvta_s(const void* p) {
    return (uint32_t)__cvta_generic_to_shared(p);
}
__device__ __forceinline__ void cp16(uint32_t s, const void* g) {
    asm volatile("cp.async.cg.shared.global [%0],[%1],16;" :: "r"(s), "l"(g));
}
__device__ __forceinline__ void cp8(uint32_t s, const void* g) {
    asm volatile("cp.async.ca.shared.global [%0],[%1],8;" :: "r"(s), "l"(g));
}
#define CP_COMMIT() asm volatile("cp.async.commit_group;")
#define CP_WAIT1()  asm volatile("cp.async.wait_group 1;")
#define CP_WAIT0()  asm volatile("cp.async.wait_group 0;")

__device__ __forceinline__ void mma8(float* c, const uint32_t* a, const uint32_t* b) {
    asm volatile(
        "mma.sync.aligned.m16n8k8.row.col.f32.tf32.tf32.f32 "
        "{%0,%1,%2,%3}, {%4,%5,%6,%7}, {%8,%9}, {%0,%1,%2,%3};"
        : "+f"(c[0]), "+f"(c[1]), "+f"(c[2]), "+f"(c[3])
        : "r"(a[0]), "r"(a[1]), "r"(a[2]), "r"(a[3]), "r"(b[0]), "r"(b[1]));
}

// ---------------------------------------------------------------------------
// 0) conv1 weight prep: [256][650] -> [256][672] zero-padded
// ---------------------------------------------------------------------------
__global__ void prep_w1(const float* __restrict__ w)
{
    int idx = blockIdx.x * 256 + threadIdx.x;
    if (idx >= W_ * K1P_) return;
    int m = idx / K1P_, k = idx - m * K1P_;
    g_w1[idx] = (k < K1_) ? w[m * K1_ + k] : 0.f;
}

// ---------------------------------------------------------------------------
// 1) embedding + position features -> g_h [B, L, 130]
// ---------------------------------------------------------------------------
__global__ void embed_kernel(const int* __restrict__ x,
                             const float* __restrict__ pe,
                             const float* __restrict__ emb)
{
    int bl = blockIdx.x;
    int d  = threadIdx.x;
    float v;
    if (d < 128) {
        int tok = x[bl];
        v = emb[(size_t)tok * 128 + d];
    } else {
        v = pe[bl * 2 + (d - 128)];
    }
    g_h[(size_t)bl * D_ + d] = v;
}

// ---------------------------------------------------------------------------
// 2) conv1: per-batch GEMM [256 x 672] @ [672 x 508] (K zero-padded)
//    A = g_w1 row-major [m][k]; B column n = contiguous window g_h + n*130.
//    Raw fp32 bits fed to tf32 MMA (RZ truncation). cp.async 2-stage.
//    Block 128x128, BK=32, 8 warps, warp tile 64x32.
//    smem: As[2][128][36], Bs[2][128][36] (both [row][k]) = 73728 B dynamic.
// ---------------------------------------------------------------------------
#define C1_NIT (K1P_ / 32)
__global__ __launch_bounds__(256, 2) void conv1_tc(
    const float* __restrict__ bias,
    const float* __restrict__ bg, const float* __restrict__ bb,
    const float* __restrict__ bmu, const float* __restrict__ bvv,
    const float* __restrict__ pw)
{
    extern __shared__ uint32_t sm[];
    uint32_t sbase = cvta_s(sm);
    int b  = blockIdx.z;
    const float* hb = g_h + (size_t)b * (L_ * D_);
    int n0 = blockIdx.x * 128;
    int m0 = blockIdx.y * 128;
    int t = threadIdx.x, lane = t & 31, wid = t >> 5;
    int wm = wid >> 2, wn = wid & 3;
    int fr = lane >> 2, fc = lane & 3;

    float acc[4][4][4];
    #pragma unroll
    for (int i = 0; i < 4; i++)
        #pragma unroll
        for (int j = 0; j < 4; j++)
            #pragma unroll
            for (int q = 0; q < 4; q++) acc[i][j][q] = 0.f;

    int arow = t >> 1, akg = (t & 1) * 16;
    int brow = t >> 1, bkg = (t & 1) * 16;
    const float* arp = g_w1 + (size_t)(m0 + arow) * K1P_ + akg;
    const float* brp = hb + (size_t)(n0 + brow) * D_ + bkg;   // stays in-bounds (pad)
    uint32_t a_s0 = sbase + (arow * 36 + akg) * 4;
    uint32_t b_s0 = sbase + (9216 + brow * 36 + bkg) * 4;

    // prologue: stage 0
    {
        #pragma unroll
        for (int q = 0; q < 4; q++) cp16(a_s0 + 16 * q, arp + 4 * q);
        #pragma unroll
        for (int q = 0; q < 8; q++) cp8(b_s0 + 8 * q, brp + 2 * q);
        CP_COMMIT();
    }

    for (int it = 0; it < C1_NIT; it++) {
        int cur = it & 1;
        if (it + 1 < C1_NIT) {
            int nk = (it + 1) * 32;
            uint32_t a_s = a_s0 + (cur ^ 1) * 4608 * 4;
            uint32_t b_s = b_s0 + (cur ^ 1) * 4608 * 4;
            #pragma unroll
            for (int q = 0; q < 4; q++) cp16(a_s + 16 * q, arp + nk + 4 * q);
            #pragma unroll
            for (int q = 0; q < 8; q++) cp8(b_s + 8 * q, brp + nk + 2 * q);
            CP_COMMIT();
            CP_WAIT1();
        } else {
            CP_WAIT0();
        }
        __syncthreads();

        const uint32_t* As = sm + cur * 4608;
        const uint32_t* Bs = sm + 9216 + cur * 4608;
        #pragma unroll
        for (int kk = 0; kk < 32; kk += 8) {
            uint32_t af[4][4], bf[4][2];
            #pragma unroll
            for (int i = 0; i < 4; i++) {
                int m = wm * 64 + 16 * i + fr;
                af[i][0] = As[m * 36 + kk + fc];
                af[i][1] = As[(m + 8) * 36 + kk + fc];
                af[i][2] = As[m * 36 + kk + fc + 4];
                af[i][3] = As[(m + 8) * 36 + kk + fc + 4];
            }
            #pragma unroll
            for (int j = 0; j < 4; j++) {
                int n = wn * 32 + 8 * j + fr;
                bf[j][0] = Bs[n * 36 + kk + fc];
                bf[j][1] = Bs[n * 36 + kk + fc + 4];
            }
            #pragma unroll
            for (int i = 0; i < 4; i++)
                #pragma unroll
                for (int j = 0; j < 4; j++)
                    mma8(acc[i][j], af[i], bf[j]);
        }
        __syncthreads();
    }

    float p = pw[0];
    #pragma unroll
    for (int i = 0; i < 4; i++) {
        int r0 = m0 + wm * 64 + 16 * i + fr;
        int r1 = r0 + 8;
        float s0 = rsqrtf(bvv[r0] + EPSF) * bg[r0];
        float o0 = bb[r0] - bmu[r0] * s0;
        float bi0 = bias[r0];
        float s1 = rsqrtf(bvv[r1] + EPSF) * bg[r1];
        float o1 = bb[r1] - bmu[r1] * s1;
        float bi1 = bias[r1];
        #pragma unroll
        for (int j = 0; j < 4; j++) {
            int c = n0 + wn * 32 + 8 * j + 2 * fc;
            if (c < Lp_) {
                float v0 = (acc[i][j][0] + bi0) * s0 + o0;
                float v1 = (acc[i][j][1] + bi0) * s0 + o0;
                float v2 = (acc[i][j][2] + bi1) * s1 + o1;
                float v3 = (acc[i][j][3] + bi1) * s1 + o1;
                v0 = v0 > 0.f ? v0 : p * v0;
                v1 = v1 > 0.f ? v1 : p * v1;
                v2 = v2 > 0.f ? v2 : p * v2;
                v3 = v3 > 0.f ? v3 : p * v3;
                size_t o_a = (size_t)r0 * NB_ + (size_t)b * Lp_ + c;
                size_t o_b = (size_t)r1 * NB_ + (size_t)b * Lp_ + c;
                *(float2*)(g_y  + o_a) = make_float2(v0, v1);
                *(float2*)(g_xI + o_a) = make_float2(v0, v1);
                *(float2*)(g_y  + o_b) = make_float2(v2, v3);
                *(float2*)(g_xI + o_b) = make_float2(v2, v3);
            }
        }
    }
}

// ---------------------------------------------------------------------------
// 3) conv-block GEMM: g_z = cb_w_i[256x256] @ g_y[256x65024] + bias
//    cp.async 2-stage, raw fp32 -> tf32. smem As[2][128][36], Bs[2][32][132].
// ---------------------------------------------------------------------------
#define CB_NIT (W_ / 32)
__global__ __launch_bounds__(256, 2) void cb_tc(
    const float* __restrict__ A, const float* __restrict__ bias)
{
    extern __shared__ uint32_t sm[];
    uint32_t sbase = cvta_s(sm);
    int n0 = blockIdx.x * 128;
    int m0 = blockIdx.y * 128;
    int t = threadIdx.x, lane = t & 31, wid = t >> 5;
    int wm = wid >> 2, wn = wid & 3;
    int fr = lane >> 2, fc = lane & 3;

    float acc[4][4][4];
    #pragma unroll
    for (int i = 0; i < 4; i++)
        #pragma unroll
        for (int j = 0; j < 4; j++)
            #pragma unroll
            for (int q = 0; q < 4; q++) acc[i][j][q] = 0.f;

    int arow = t >> 1, akg = (t & 1) * 16;
    int bk = t >> 3, bng = (t & 7) * 16;
    const float* arp = A + (size_t)(m0 + arow) * W_ + akg;
    const float* brp = g_y + (size_t)bk * NB_ + n0 + bng;
    uint32_t a_s0 = sbase + (arow * 36 + akg) * 4;
    uint32_t b_s0 = sbase + (9216 + bk * 132 + bng) * 4;

    {
        #pragma unroll
        for (int q = 0; q < 4; q++) cp16(a_s0 + 16 * q, arp + 4 * q);
        #pragma unroll
        for (int q = 0; q < 4; q++) cp16(b_s0 + 16 * q, brp + 4 * q);
        CP_COMMIT();
    }

    for (int it = 0; it < CB_NIT; it++) {
        int cur = it & 1;
        if (it + 1 < CB_NIT) {
            int nk = (it + 1) * 32;
            uint32_t a_s = a_s0 + (cur ^ 1) * 4608 * 4;
            uint32_t b_s = b_s0 + (cur ^ 1) * 4224 * 4;
            const float* ag = arp + nk;
            const float* bg2 = brp + (size_t)nk * NB_;
            #pragma unroll
            for (int q = 0; q < 4; q++) cp16(a_s + 16 * q, ag + 4 * q);
            #pragma unroll
            for (int q = 0; q < 4; q++) cp16(b_s + 16 * q, bg2 + 4 * q);
            CP_COMMIT();
            CP_WAIT1();
        } else {
            CP_WAIT0();
        }
        __syncthreads();

        const uint32_t* As = sm + cur * 4608;
        const uint32_t* Bs = sm + 9216 + cur * 4224;
        #pragma unroll
        for (int kk = 0; kk < 32; kk += 8) {
            uint32_t af[4][4], bf[4][2];
            #pragma unroll
            for (int i = 0; i < 4; i++) {
                int m = wm * 64 + 16 * i + fr;
                af[i][0] = As[m * 36 + kk + fc];
                af[i][1] = As[(m + 8) * 36 + kk + fc];
                af[i][2] = As[m * 36 + kk + fc + 4];
                af[i][3] = As[(m + 8) * 36 + kk + fc + 4];
            }
            #pragma unroll
            for (int j = 0; j < 4; j++) {
                int n = wn * 32 + 8 * j + fr;
                bf[j][0] = Bs[(kk + fc) * 132 + n];
                bf[j][1] = Bs[(kk + fc + 4) * 132 + n];
            }
            #pragma unroll
            for (int i = 0; i < 4; i++)
                #pragma unroll
                for (int j = 0; j < 4; j++)
                    mma8(acc[i][j], af[i], bf[j]);
        }
        __syncthreads();
    }

    #pragma unroll
    for (int i = 0; i < 4; i++) {
        int r0 = m0 + wm * 64 + 16 * i + fr;
        int r1 = r0 + 8;
        float bi0 = bias[r0], bi1 = bias[r1];
        #pragma unroll
        for (int j = 0; j < 4; j++) {
            int c = n0 + wn * 32 + 8 * j + 2 * fc;
            *(float2*)(g_z + (size_t)r0 * NB_ + c) =
                make_float2(acc[i][j][0] + bi0, acc[i][j][1] + bi0);
            *(float2*)(g_z + (size_t)r1 * NB_ + c) =
                make_float2(acc[i][j][2] + bi1, acc[i][j][3] + bi1);
        }
    }
}

// ---------------------------------------------------------------------------
// 4) GroupNorm stats per (b, g)
// ---------------------------------------------------------------------------
__global__ void gnstats_kernel()
{
    __shared__ float ss[256];
    __shared__ float sq[256];
    int g = blockIdx.x, b = blockIdx.y, t = threadIdx.x;
    int c = t >> 2;
    int q0 = t & 3;
    const float4* row = (const float4*)(g_z + (size_t)(g * GC_ + c) * NB_ + (size_t)b * Lp_);
    float s = 0.f, q = 0.f;
    for (int i = q0; i < 127; i += 4) {
        float4 v = row[i];
        s += v.x + v.y + v.z + v.w;
        q += v.x * v.x + v.y * v.y + v.z * v.z + v.w * v.w;
    }
    ss[t] = s; sq[t] = q;
    __syncthreads();
    for (int o = 128; o > 0; o >>= 1) {
        if (t < o) { ss[t] += ss[t + o]; sq[t] += sq[t + o]; }
        __syncthreads();
    }
    if (t == 0) {
        float cnt  = (float)(GC_ * Lp_);
        float mean = ss[0] / cnt;
        float var  = sq[0] / cnt - mean * mean;
        g_stats[b * G_ + g] = make_float2(mean, rsqrtf(var + EPSF));
    }
}

// ---------------------------------------------------------------------------
// 5) GroupNorm apply + PReLU + residual (float4; 508 and 65024 are mult of 4)
// ---------------------------------------------------------------------------
__global__ void gnapply_kernel(const float* __restrict__ gamma,
                               const float* __restrict__ beta,
                               const float* __restrict__ pp)
{
    unsigned i4 = blockIdx.x * 256u + threadIdx.x;
    if (i4 >= (unsigned)(W_ * NB_ / 4)) return;
    unsigned idx = i4 * 4;
    unsigned w = idx / NB_;
    unsigned r = idx - w * NB_;
    unsigned b = r / Lp_;
    float2 st = g_stats[b * G_ + (w >> 6)];
    float ga = gamma[w] * st.y;
    float be = beta[w] - st.x * ga;
    float p = pp[0];
    float4 z = *(const float4*)(g_z + idx);
    float4 y = *(const float4*)(g_y + idx);
    float v;
    v = z.x * ga + be; y.x += (v > 0.f ? v : p * v);
    v = z.y * ga + be; y.y += (v > 0.f ? v : p * v);
    v = z.z * ga + be; y.z += (v > 0.f ? v : p * v);
    v = z.w * ga + be; y.w += (v > 0.f ? v : p * v);
    *(float4*)(g_y + idx) = y;
}

// ---------------------------------------------------------------------------
// 6) final residual + masked segment max -> g_feat [B, 3*W]
// ---------------------------------------------------------------------------
__global__ void maxfeat_kernel(const int* __restrict__ posE)
{
    int gw   = (blockIdx.x * blockDim.x + threadIdx.x) >> 5;
    int lane = threadIdx.x & 31;
    if (gw >= B_ * W_) return;
    int b = gw >> 8;
    int w = gw & 255;
    int p0 = posE[b * 2] + 1;
    int p1 = posE[b * 2 + 1] + 1;
    const float* yr = g_y  + (size_t)w * NB_ + (size_t)b * Lp_;
    const float* xr = g_xI + (size_t)w * NB_ + (size_t)b * Lp_;
    float m1 = FNEG, m2 = FNEG, m3 = FNEG;
    for (int l = lane; l < Lp_; l += 32) {
        float v = yr[l] + xr[l];
        float a1 = v + ((l >= p0) ? NEGF : 0.f);
        float a2 = v + ((l < p0 || l >= p1) ? NEGF : 0.f);
        float a3 = v + ((l < p1) ? NEGF : 0.f);
        m1 = fmaxf(m1, a1);
        m2 = fmaxf(m2, a2);
        m3 = fmaxf(m3, a3);
    }
    #pragma unroll
    for (int o = 16; o > 0; o >>= 1) {
        m1 = fmaxf(m1, __shfl_down_sync(0xffffffffu, m1, o));
        m2 = fmaxf(m2, __shfl_down_sync(0xffffffffu, m2, o));
        m3 = fmaxf(m3, __shfl_down_sync(0xffffffffu, m3, o));
    }
    if (lane == 0) {
        g_feat[b * 3 * W_ + 0 * W_ + w] = m1;
        g_feat[b * 3 * W_ + 1 * W_ + w] = m2;
        g_feat[b * 3 * W_ + 2 * W_ + w] = m3;
    }
}

// ---------------------------------------------------------------------------
// 7) dense head + softmax
// ---------------------------------------------------------------------------
__global__ void dense_kernel(
    const float* __restrict__ d0w, const float* __restrict__ d0b,
    const float* __restrict__ d1w, const float* __restrict__ d1b,
    const float* __restrict__ bndg, const float* __restrict__ bndb,
    const float* __restrict__ bndm, const float* __restrict__ bndv,
    const float* __restrict__ pd,
    const float* __restrict__ finw, const float* __restrict__ finb,
    float* __restrict__ out)
{
    __shared__ float sf[3 * W_];
    __shared__ float sh[W_];
    __shared__ float sl[LBL_];
    __shared__ float red[2];
    int b = blockIdx.x, t = threadIdx.x;

    for (int i = t; i < 3 * W_; i += 256) sf[i] = g_feat[b * 3 * W_ + i];
    __syncthreads();

    float acc = d0b[t];
    {
        const float* wr = d0w + t * (3 * W_);
        #pragma unroll 8
        for (int k = 0; k < 3 * W_; k++) acc += sf[k] * wr[k];
    }
    acc = (acc - bndm[t]) * rsqrtf(bndv[t] + EPSF) * bndg[t] + bndb[t];
    { float p = pd[0]; acc = acc > 0.f ? acc : p * acc; }
    sh[t] = acc;
    __syncthreads();

    float a2 = d1b[t];
    {
        const float* wr = d1w + t * W_;
        #pragma unroll 8
        for (int k = 0; k < W_; k++) a2 += sh[k] * wr[k];
    }
    a2 = (a2 - bndm[W_ + t]) * rsqrtf(bndv[W_ + t] + EPSF) * bndg[W_ + t] + bndb[W_ + t];
    { float p = pd[1]; a2 = a2 > 0.f ? a2 : p * a2; }
    __syncthreads();
    sh[t] = a2;
    __syncthreads();

    if (t < LBL_) {
        float a3 = finb[t];
        const float* wr = finw + t * W_;
        #pragma unroll 8
        for (int k = 0; k < W_; k++) a3 += sh[k] * wr[k];
        sl[t] = a3;
    }
    __syncthreads();
    if (t == 0) {
        float mx = FNEG;
        for (int i = 0; i < LBL_; i++) mx = fmaxf(mx, sl[i]);
        float s = 0.f;
        for (int i = 0; i < LBL_; i++) s += expf(sl[i] - mx);
        red[0] = mx;
        red[1] = 1.f / s;
    }
    __syncthreads();
    if (t < LBL_) out[b * LBL_ + t] = expf(sl[t] - red[0]) * red[1];
}

// ---------------------------------------------------------------------------
// launch
// ---------------------------------------------------------------------------
extern "C" void kernel_launch(void* const* d_in, const int* in_sizes, int n_in,
                              void* d_out, int out_size)
{
    const int*   x      = (const int*)d_in[0];
    const int*   posE   = (const int*)d_in[1];
    const float* pe     = (const float*)d_in[2];
    const float* emb    = (const float*)d_in[3];
    const float* c1w    = (const float*)d_in[4];
    const float* c1b    = (const float*)d_in[5];
    const float* bn1g   = (const float*)d_in[6];
    const float* bn1b   = (const float*)d_in[7];
    const float* bn1m   = (const float*)d_in[8];
    const float* bn1v   = (const float*)d_in[9];
    const float* p1w    = (const float*)d_in[10];
    const float* cbw    = (const float*)d_in[11];
    const float* cbb    = (const float*)d_in[12];
    const float* gng    = (const float*)d_in[13];
    const float* gnb    = (const float*)d_in[14];
    const float* cbp    = (const float*)d_in[15];
    const float* d0w    = (const float*)d_in[16];
    const float* d0b    = (const float*)d_in[17];
    const float* d1w    = (const float*)d_in[18];
    const float* d1b    = (const float*)d_in[19];
    const float* bndg   = (const float*)d_in[20];
    const float* bndb   = (const float*)d_in[21];
    const float* bndm   = (const float*)d_in[22];
    const float* bndv   = (const float*)d_in[23];
    const float* pd     = (const float*)d_in[24];
    const float* finw   = (const float*)d_in[25];
    const float* finb   = (const float*)d_in[26];
    float* out = (float*)d_out;

    const int C1_SMEM = 2 * (4608 + 4608) * 4;   // 73728 B
    const int CB_SMEM = 2 * (4608 + 4224) * 4;   // 70656 B
    cudaFuncSetAttribute(conv1_tc, cudaFuncAttributeMaxDynamicSharedMemorySize, C1_SMEM);
    cudaFuncSetAttribute(cb_tc,    cudaFuncAttributeMaxDynamicSharedMemorySize, CB_SMEM);

    prep_w1<<<(W_ * K1P_ + 255) / 256, 256>>>(c1w);
    embed_kernel<<<B_ * L_, D_>>>(x, pe, emb);

    {
        dim3 grid((Lp_ + 127) / 128, W_ / 128, B_);   // (4, 2, 128)
        conv1_tc<<<grid, 256, C1_SMEM>>>(c1b, bn1g, bn1b, bn1m, bn1v, p1w);
    }

    for (int i = 0; i < CN_; i++) {
        dim3 gridg(NB_ / 128, W_ / 128);              // (508, 2)
        cb_tc<<<gridg, 256, CB_SMEM>>>(cbw + (size_t)i * W_ * W_, cbb + i * W_);
        dim3 grids(G_, B_);
        gnstats_kernel<<<grids, 256>>>();
        gnapply_kernel<<<(W_ * NB_ / 4 + 255) / 256, 256>>>(gng + i * W_, gnb + i * W_, cbp + i);
    }

    {
        int warps = B_ * W_;
        int threads = warps * 32;
        maxfeat_kernel<<<(threads + 255) / 256, 256>>>(posE);
    }

    dense_kernel<<<B_, 256>>>(d0w, d0b, d1w, d1b, bndg, bndb, bndm, bndv,
                              pd, finw, finb, out);

    (void)in_sizes; (void)n_in; (void)out_size;
}

// round 4
// speedup vs baseline: 3.6782x; 1.4204x over previous
#include <cuda_runtime.h>
#include <cuda_bf16.h>
#include <cstdint>

// Problem constants
#define B_   128
#define L_   512
#define D_   130            // E + 2
#define W_   256
#define KH_  5
#define CN_  4
#define G_   4
#define GC_  64             // W_/G_
#define Lp_  508            // L - KH + 1
#define NB_  65024          // B_*Lp_
#define K1_  650            // KH_*D_
#define K1P_ 672            // padded K for conv1 (21 * 32)
#define LBL_ 53
#define EPSF 1e-5f
#define NEGF (-100000.0f)
#define FNEG (-3.0e38f)

#define HPL_ 65             // b32 (bf16-pairs) per l position (130/2)

// Scratch (static device memory -- no allocations allowed)
__device__ uint32_t g_hh[(size_t)B_ * L_ * HPL_ + 1024]; // bf16-pair h
__device__ uint32_t g_w1h[(size_t)W_ * (K1P_ / 2)];      // conv1 w, bf16 pair-interleaved
__device__ uint32_t g_cbwh[(size_t)CN_ * W_ * (W_ / 2)]; // cb w, bf16 pair-interleaved
__device__ uint32_t g_yh[(size_t)(W_ / 2) * NB_];        // y bf16, [wpair][nb]
__device__ float    g_y[(size_t)W_ * NB_];               // [w][b*Lp+l]
__device__ float    g_z[(size_t)W_ * NB_];
__device__ float    g_xI[(size_t)W_ * NB_];
__device__ float2   g_stats[B_ * G_];                    // (mean, rstd)
__device__ float    g_feat[B_ * 3 * W_];

// ---------------------------------------------------------------------------
// helpers
// ---------------------------------------------------------------------------
__device__ __forceinline__ uint32_t cvta_s(const void* p) {
    return (uint32_t)__cvta_generic_to_shared(p);
}
__device__ __forceinline__ void cp16(uint32_t s, const void* g) {
    asm volatile("cp.async.cg.shared.global [%0],[%1],16;" :: "r"(s), "l"(g));
}
__device__ __forceinline__ void cp4(uint32_t s, const void* g) {
    asm volatile("cp.async.ca.shared.global [%0],[%1],4;" :: "r"(s), "l"(g));
}
#define CP_COMMIT() asm volatile("cp.async.commit_group;")
#define CP_WAIT1()  asm volatile("cp.async.wait_group 1;")
#define CP_WAIT0()  asm volatile("cp.async.wait_group 0;")

__device__ __forceinline__ void mma16(float* c, const uint32_t* a, const uint32_t* b) {
    asm volatile(
        "mma.sync.aligned.m16n8k16.row.col.f32.bf16.bf16.f32 "
        "{%0,%1,%2,%3}, {%4,%5,%6,%7}, {%8,%9}, {%0,%1,%2,%3};"
        : "+f"(c[0]), "+f"(c[1]), "+f"(c[2]), "+f"(c[3])
        : "r"(a[0]), "r"(a[1]), "r"(a[2]), "r"(a[3]), "r"(b[0]), "r"(b[1]));
}

__device__ __forceinline__ uint32_t packbf(float lo, float hi) {
    __nv_bfloat162 t = __floats2bfloat162_rn(lo, hi);   // .x = lo (low half)
    return *(uint32_t*)&t;
}

// ---------------------------------------------------------------------------
// 0a) conv1 weight prep: [256][650] fp32 -> [256][336] bf16-pair, zero padded
// ---------------------------------------------------------------------------
__global__ void prep_w1h(const float* __restrict__ w)
{
    int idx = blockIdx.x * 256 + threadIdx.x;
    if (idx >= W_ * (K1P_ / 2)) return;
    int m = idx / (K1P_ / 2), kp = idx - m * (K1P_ / 2);
    int k0 = 2 * kp, k1 = k0 + 1;
    float a = (k0 < K1_) ? w[m * K1_ + k0] : 0.f;
    float b = (k1 < K1_) ? w[m * K1_ + k1] : 0.f;
    g_w1h[idx] = packbf(a, b);
}

// ---------------------------------------------------------------------------
// 0b) cb weight prep: [4][256][256] fp32 -> [4][256][128] bf16-pair
// ---------------------------------------------------------------------------
__global__ void prep_cbwh(const float* __restrict__ w)
{
    int idx = blockIdx.x * 256 + threadIdx.x;
    if (idx >= CN_ * W_ * (W_ / 2)) return;
    int row = idx >> 7;              // i*W_+m
    int kp  = idx & 127;
    const float* src = w + (size_t)row * W_ + 2 * kp;
    g_cbwh[idx] = packbf(src[0], src[1]);
}

// ---------------------------------------------------------------------------
// 1) embedding + position features -> g_hh bf16 pairs [B*L][65]
// ---------------------------------------------------------------------------
__global__ void embed_h(const int* __restrict__ x,
                        const float* __restrict__ pe,
                        const float* __restrict__ emb)
{
    int id = blockIdx.x * 256 + threadIdx.x;
    if (id >= B_ * L_ * HPL_) return;
    int bl = id / HPL_, t = id - bl * HPL_;
    float v0, v1;
    if (t < 64) {
        int tok = x[bl];
        const float* e = emb + (size_t)tok * 128 + 2 * t;
        v0 = e[0]; v1 = e[1];
    } else {
        v0 = pe[bl * 2]; v1 = pe[bl * 2 + 1];
    }
    g_hh[id] = packbf(v0, v1);
}

// ---------------------------------------------------------------------------
// 2) conv1: per-batch GEMM [256 x 672] @ [672 x 508], bf16 m16n8k16.
//    A pair-interleaved [m][336]; B column n = contiguous window g_hh+n*65.
//    3-stage cp.async. Block 128x128, BK=32(bf16)=16(b32), 8 warps, warp 64x32.
//    smem b32: As 3*128*20, Bs 3*128*20 -> 15360 b32 = 61440 B.
// ---------------------------------------------------------------------------
#define C1_NIT 21
__global__ __launch_bounds__(256, 2) void conv1_tc(
    const float* __restrict__ bias,
    const float* __restrict__ bg, const float* __restrict__ bb,
    const float* __restrict__ bmu, const float* __restrict__ bvv,
    const float* __restrict__ pw)
{
    extern __shared__ uint32_t sm[];
    uint32_t sb = cvta_s(sm);
    int b  = blockIdx.z;
    int n0 = blockIdx.x * 128;
    int m0 = blockIdx.y * 128;
    int t = threadIdx.x, lane = t & 31, wid = t >> 5;
    int wm = wid >> 2, wn = wid & 3;
    int fr = lane >> 2, fc = lane & 3;

    float acc[4][4][4];
    #pragma unroll
    for (int i = 0; i < 4; i++)
        #pragma unroll
        for (int j = 0; j < 4; j++)
            #pragma unroll
            for (int q = 0; q < 4; q++) acc[i][j][q] = 0.f;

    int arow = t >> 1, ah = (t & 1) * 8;
    const uint32_t* agp = g_w1h + (size_t)(m0 + arow) * (K1P_ / 2) + ah;
    const uint32_t* bgp = g_hh + (size_t)b * (L_ * HPL_) + (size_t)(n0 + arow) * HPL_ + ah;
    uint32_t aS = sb + (arow * 20 + ah) * 4;
    uint32_t bS = sb + (7680 + arow * 20 + ah) * 4;

    #define C1_ISSUE(it_) do { \
        int s_ = (it_) % 3; int kt_ = (it_) * 16; \
        uint32_t as_ = aS + s_ * 2560 * 4, bs_ = bS + s_ * 2560 * 4; \
        cp16(as_, agp + kt_); cp16(as_ + 16, agp + kt_ + 4); \
        _Pragma("unroll") \
        for (int q_ = 0; q_ < 8; q_++) cp4(bs_ + 4 * q_, bgp + kt_ + q_); \
    } while (0)

    C1_ISSUE(0); CP_COMMIT();
    C1_ISSUE(1); CP_COMMIT();

    for (int it = 0; it < C1_NIT; it++) {
        if (it < C1_NIT - 1) CP_WAIT1(); else CP_WAIT0();
        __syncthreads();
        const uint32_t* as = sm + (it % 3) * 2560;
        const uint32_t* bs = sm + 7680 + (it % 3) * 2560;
        #pragma unroll
        for (int ss = 0; ss < 2; ss++) {
            int kp = ss * 8;
            uint32_t af[4][4], bf[4][2];
            #pragma unroll
            for (int i = 0; i < 4; i++) {
                int m = wm * 64 + 16 * i + fr;
                af[i][0] = as[m * 20 + kp + fc];
                af[i][1] = as[(m + 8) * 20 + kp + fc];
                af[i][2] = as[m * 20 + kp + 4 + fc];
                af[i][3] = as[(m + 8) * 20 + kp + 4 + fc];
            }
            #pragma unroll
            for (int j = 0; j < 4; j++) {
                int n = wn * 32 + 8 * j + fr;
                bf[j][0] = bs[n * 20 + kp + fc];
                bf[j][1] = bs[n * 20 + kp + 4 + fc];
            }
            #pragma unroll
            for (int i = 0; i < 4; i++)
                #pragma unroll
                for (int j = 0; j < 4; j++)
                    mma16(acc[i][j], af[i], bf[j]);
        }
        if (it + 2 < C1_NIT) { C1_ISSUE(it + 2); CP_COMMIT(); }
    }

    float p = pw[0];
    #pragma unroll
    for (int i = 0; i < 4; i++) {
        int r0 = m0 + wm * 64 + 16 * i + fr;
        int r1 = r0 + 8;
        float s0 = rsqrtf(bvv[r0] + EPSF) * bg[r0];
        float o0 = bb[r0] - bmu[r0] * s0;
        float bi0 = bias[r0];
        float s1 = rsqrtf(bvv[r1] + EPSF) * bg[r1];
        float o1 = bb[r1] - bmu[r1] * s1;
        float bi1 = bias[r1];
        #pragma unroll
        for (int j = 0; j < 4; j++) {
            int c = n0 + wn * 32 + 8 * j + 2 * fc;
            float v0 = (acc[i][j][0] + bi0) * s0 + o0;
            float v1 = (acc[i][j][1] + bi0) * s0 + o0;
            float v2 = (acc[i][j][2] + bi1) * s1 + o1;
            float v3 = (acc[i][j][3] + bi1) * s1 + o1;
            v0 = v0 > 0.f ? v0 : p * v0;
            v1 = v1 > 0.f ? v1 : p * v1;
            v2 = v2 > 0.f ? v2 : p * v2;
            v3 = v3 > 0.f ? v3 : p * v3;
            // partner lane (fr^1) holds rows r0^1 / r1^1 at same columns
            float q0 = __shfl_xor_sync(0xffffffffu, v0, 4);
            float q1 = __shfl_xor_sync(0xffffffffu, v1, 4);
            float q2 = __shfl_xor_sync(0xffffffffu, v2, 4);
            float q3 = __shfl_xor_sync(0xffffffffu, v3, 4);
            if (c < Lp_) {
                size_t col = (size_t)b * Lp_ + c;
                *(float2*)(g_y  + (size_t)r0 * NB_ + col) = make_float2(v0, v1);
                *(float2*)(g_xI + (size_t)r0 * NB_ + col) = make_float2(v0, v1);
                *(float2*)(g_y  + (size_t)r1 * NB_ + col) = make_float2(v2, v3);
                *(float2*)(g_xI + (size_t)r1 * NB_ + col) = make_float2(v2, v3);
                if (!(fr & 1)) {   // even row: pack (r, r+1) pairs
                    uint2 u0; u0.x = packbf(v0, q0); u0.y = packbf(v1, q1);
                    *(uint2*)(g_yh + (size_t)(r0 >> 1) * NB_ + col) = u0;
                    uint2 u1; u1.x = packbf(v2, q2); u1.y = packbf(v3, q3);
                    *(uint2*)(g_yh + (size_t)(r1 >> 1) * NB_ + col) = u1;
                }
            }
        }
    }
}

// ---------------------------------------------------------------------------
// 3) conv-block GEMM: g_z = cb_w_i[256x256] @ y[256x65024] + bias, bf16.
//    A pair-interleaved [m][128]; B = g_yh [wpair][nb].
//    smem b32: As 3*128*20 = 7680, Bs 3*16*136 = 6528 -> 56832 B.
// ---------------------------------------------------------------------------
#define CB_NIT 8
__global__ __launch_bounds__(256, 2) void cb_tc(int blk, const float* __restrict__ bias)
{
    extern __shared__ uint32_t sm[];
    uint32_t sb = cvta_s(sm);
    const uint32_t* A = g_cbwh + (size_t)blk * W_ * (W_ / 2);
    int n0 = blockIdx.x * 128;
    int m0 = blockIdx.y * 128;
    int t = threadIdx.x, lane = t & 31, wid = t >> 5;
    int wm = wid >> 2, wn = wid & 3;
    int fr = lane >> 2, fc = lane & 3;

    float acc[4][4][4];
    #pragma unroll
    for (int i = 0; i < 4; i++)
        #pragma unroll
        for (int j = 0; j < 4; j++)
            #pragma unroll
            for (int q = 0; q < 4; q++) acc[i][j][q] = 0.f;

    int arow = t >> 1, ah = (t & 1) * 8;
    int brow = t >> 4, bc = (t & 15) * 8;
    const uint32_t* agp = A + (size_t)(m0 + arow) * (W_ / 2) + ah;
    const uint32_t* bgp = g_yh + (size_t)brow * NB_ + n0 + bc;
    uint32_t aS = sb + (arow * 20 + ah) * 4;
    uint32_t bS = sb + (7680 + brow * 136 + bc) * 4;

    #define CB_ISSUE(it_) do { \
        int s_ = (it_) % 3; \
        uint32_t as_ = aS + s_ * 2560 * 4, bs_ = bS + s_ * 2176 * 4; \
        const uint32_t* ag_ = agp + (it_) * 16; \
        const uint32_t* bg_ = bgp + (size_t)(it_) * 16 * NB_; \
        cp16(as_, ag_); cp16(as_ + 16, ag_ + 4); \
        cp16(bs_, bg_); cp16(bs_ + 16, bg_ + 4); \
    } while (0)

    CB_ISSUE(0); CP_COMMIT();
    CB_ISSUE(1); CP_COMMIT();

    for (int it = 0; it < CB_NIT; it++) {
        if (it < CB_NIT - 1) CP_WAIT1(); else CP_WAIT0();
        __syncthreads();
        const uint32_t* as = sm + (it % 3) * 2560;
        const uint32_t* bs = sm + 7680 + (it % 3) * 2176;
        #pragma unroll
        for (int ss = 0; ss < 2; ss++) {
            int kp = ss * 8;
            uint32_t af[4][4], bf[4][2];
            #pragma unroll
            for (int i = 0; i < 4; i++) {
                int m = wm * 64 + 16 * i + fr;
                af[i][0] = as[m * 20 + kp + fc];
                af[i][1] = as[(m + 8) * 20 + kp + fc];
                af[i][2] = as[m * 20 + kp + 4 + fc];
                af[i][3] = as[(m + 8) * 20 + kp + 4 + fc];
            }
            #pragma unroll
            for (int j = 0; j < 4; j++) {
                int n = wn * 32 + 8 * j + fr;
                bf[j][0] = bs[(kp + fc) * 136 + n];
                bf[j][1] = bs[(kp + 4 + fc) * 136 + n];
            }
            #pragma unroll
            for (int i = 0; i < 4; i++)
                #pragma unroll
                for (int j = 0; j < 4; j++)
                    mma16(acc[i][j], af[i], bf[j]);
        }
        if (it + 2 < CB_NIT) { CB_ISSUE(it + 2); CP_COMMIT(); }
    }

    #pragma unroll
    for (int i = 0; i < 4; i++) {
        int r0 = m0 + wm * 64 + 16 * i + fr;
        int r1 = r0 + 8;
        float bi0 = bias[r0], bi1 = bias[r1];
        #pragma unroll
        for (int j = 0; j < 4; j++) {
            int c = n0 + wn * 32 + 8 * j + 2 * fc;
            *(float2*)(g_z + (size_t)r0 * NB_ + c) =
                make_float2(acc[i][j][0] + bi0, acc[i][j][1] + bi0);
            *(float2*)(g_z + (size_t)r1 * NB_ + c) =
                make_float2(acc[i][j][2] + bi1, acc[i][j][3] + bi1);
        }
    }
}

// ---------------------------------------------------------------------------
// 4) GroupNorm stats per (b, g)
// ---------------------------------------------------------------------------
__global__ void gnstats_kernel()
{
    __shared__ float ss[256];
    __shared__ float sq[256];
    int g = blockIdx.x, b = blockIdx.y, t = threadIdx.x;
    int c = t >> 2;
    int q0 = t & 3;
    const float4* row = (const float4*)(g_z + (size_t)(g * GC_ + c) * NB_ + (size_t)b * Lp_);
    float s = 0.f, q = 0.f;
    for (int i = q0; i < 127; i += 4) {
        float4 v = row[i];
        s += v.x + v.y + v.z + v.w;
        q += v.x * v.x + v.y * v.y + v.z * v.z + v.w * v.w;
    }
    ss[t] = s; sq[t] = q;
    __syncthreads();
    for (int o = 128; o > 0; o >>= 1) {
        if (t < o) { ss[t] += ss[t + o]; sq[t] += sq[t + o]; }
        __syncthreads();
    }
    if (t == 0) {
        float cnt  = (float)(GC_ * Lp_);
        float mean = ss[0] / cnt;
        float var  = sq[0] / cnt - mean * mean;
        g_stats[b * G_ + g] = make_float2(mean, rsqrtf(var + EPSF));
    }
}

// ---------------------------------------------------------------------------
// 5) GroupNorm apply + PReLU + residual; processes channel pairs and also
//    emits bf16-packed g_yh for the next GEMM (unless last iteration).
// ---------------------------------------------------------------------------
__global__ void gnapply_kernel(const float* __restrict__ gamma,
                               const float* __restrict__ beta,
                               const float* __restrict__ pp, int writeH)
{
    const unsigned NQ = NB_ / 4;
    unsigned i = blockIdx.x * 256u + threadIdx.x;
    if (i >= (unsigned)(W_ / 2) * NQ) return;
    unsigned wp = i / NQ, q = i - wp * NQ;
    unsigned nb = q * 4;
    unsigned b = nb / Lp_;
    unsigned w0 = 2 * wp, w1 = w0 + 1;
    float2 st = g_stats[b * G_ + (w0 >> 6)];
    float ga0 = gamma[w0] * st.y, be0 = beta[w0] - st.x * ga0;
    float ga1 = gamma[w1] * st.y, be1 = beta[w1] - st.x * ga1;
    float p = pp[0];
    size_t o0 = (size_t)w0 * NB_ + nb, o1 = (size_t)w1 * NB_ + nb;
    float4 z0 = *(const float4*)(g_z + o0);
    float4 z1 = *(const float4*)(g_z + o1);
    float4 y0 = *(const float4*)(g_y + o0);
    float4 y1 = *(const float4*)(g_y + o1);
    float v;
    v = z0.x * ga0 + be0; y0.x += (v > 0.f ? v : p * v);
    v = z0.y * ga0 + be0; y0.y += (v > 0.f ? v : p * v);
    v = z0.z * ga0 + be0; y0.z += (v > 0.f ? v : p * v);
    v = z0.w * ga0 + be0; y0.w += (v > 0.f ? v : p * v);
    v = z1.x * ga1 + be1; y1.x += (v > 0.f ? v : p * v);
    v = z1.y * ga1 + be1; y1.y += (v > 0.f ? v : p * v);
    v = z1.z * ga1 + be1; y1.z += (v > 0.f ? v : p * v);
    v = z1.w * ga1 + be1; y1.w += (v > 0.f ? v : p * v);
    *(float4*)(g_y + o0) = y0;
    *(float4*)(g_y + o1) = y1;
    if (writeH) {
        uint4 u;
        u.x = packbf(y0.x, y1.x);
        u.y = packbf(y0.y, y1.y);
        u.z = packbf(y0.z, y1.z);
        u.w = packbf(y0.w, y1.w);
        *(uint4*)(g_yh + (size_t)wp * NB_ + nb) = u;
    }
}

// ---------------------------------------------------------------------------
// 6) final residual + masked segment max -> g_feat [B, 3*W]
// ---------------------------------------------------------------------------
__global__ void maxfeat_kernel(const int* __restrict__ posE)
{
    int gw   = (blockIdx.x * blockDim.x + threadIdx.x) >> 5;
    int lane = threadIdx.x & 31;
    if (gw >= B_ * W_) return;
    int b = gw >> 8;
    int w = gw & 255;
    int p0 = posE[b * 2] + 1;
    int p1 = posE[b * 2 + 1] + 1;
    const float* yr = g_y  + (size_t)w * NB_ + (size_t)b * Lp_;
    const float* xr = g_xI + (size_t)w * NB_ + (size_t)b * Lp_;
    float m1 = FNEG, m2 = FNEG, m3 = FNEG;
    for (int l = lane; l < Lp_; l += 32) {
        float v = yr[l] + xr[l];
        float a1 = v + ((l >= p0) ? NEGF : 0.f);
        float a2 = v + ((l < p0 || l >= p1) ? NEGF : 0.f);
        float a3 = v + ((l < p1) ? NEGF : 0.f);
        m1 = fmaxf(m1, a1);
        m2 = fmaxf(m2, a2);
        m3 = fmaxf(m3, a3);
    }
    #pragma unroll
    for (int o = 16; o > 0; o >>= 1) {
        m1 = fmaxf(m1, __shfl_down_sync(0xffffffffu, m1, o));
        m2 = fmaxf(m2, __shfl_down_sync(0xffffffffu, m2, o));
        m3 = fmaxf(m3, __shfl_down_sync(0xffffffffu, m3, o));
    }
    if (lane == 0) {
        g_feat[b * 3 * W_ + 0 * W_ + w] = m1;
        g_feat[b * 3 * W_ + 1 * W_ + w] = m2;
        g_feat[b * 3 * W_ + 2 * W_ + w] = m3;
    }
}

// ---------------------------------------------------------------------------
// 7) dense head + softmax
// ---------------------------------------------------------------------------
__global__ void dense_kernel(
    const float* __restrict__ d0w, const float* __restrict__ d0b,
    const float* __restrict__ d1w, const float* __restrict__ d1b,
    const float* __restrict__ bndg, const float* __restrict__ bndb,
    const float* __restrict__ bndm, const float* __restrict__ bndv,
    const float* __restrict__ pd,
    const float* __restrict__ finw, const float* __restrict__ finb,
    float* __restrict__ out)
{
    __shared__ float sf[3 * W_];
    __shared__ float sh[W_];
    __shared__ float sl[LBL_];
    __shared__ float red[2];
    int b = blockIdx.x, t = threadIdx.x;

    for (int i = t; i < 3 * W_; i += 256) sf[i] = g_feat[b * 3 * W_ + i];
    __syncthreads();

    float acc = d0b[t];
    {
        const float* wr = d0w + t * (3 * W_);
        #pragma unroll 8
        for (int k = 0; k < 3 * W_; k++) acc += sf[k] * wr[k];
    }
    acc = (acc - bndm[t]) * rsqrtf(bndv[t] + EPSF) * bndg[t] + bndb[t];
    { float p = pd[0]; acc = acc > 0.f ? acc : p * acc; }
    sh[t] = acc;
    __syncthreads();

    float a2 = d1b[t];
    {
        const float* wr = d1w + t * W_;
        #pragma unroll 8
        for (int k = 0; k < W_; k++) a2 += sh[k] * wr[k];
    }
    a2 = (a2 - bndm[W_ + t]) * rsqrtf(bndv[W_ + t] + EPSF) * bndg[W_ + t] + bndb[W_ + t];
    { float p = pd[1]; a2 = a2 > 0.f ? a2 : p * a2; }
    __syncthreads();
    sh[t] = a2;
    __syncthreads();

    if (t < LBL_) {
        float a3 = finb[t];
        const float* wr = finw + t * W_;
        #pragma unroll 8
        for (int k = 0; k < W_; k++) a3 += sh[k] * wr[k];
        sl[t] = a3;
    }
    __syncthreads();
    if (t == 0) {
        float mx = FNEG;
        for (int i = 0; i < LBL_; i++) mx = fmaxf(mx, sl[i]);
        float s = 0.f;
        for (int i = 0; i < LBL_; i++) s += expf(sl[i] - mx);
        red[0] = mx;
        red[1] = 1.f / s;
    }
    __syncthreads();
    if (t < LBL_) out[b * LBL_ + t] = expf(sl[t] - red[0]) * red[1];
}

// ---------------------------------------------------------------------------
// launch
// ---------------------------------------------------------------------------
extern "C" void kernel_launch(void* const* d_in, const int* in_sizes, int n_in,
                              void* d_out, int out_size)
{
    const int*   x      = (const int*)d_in[0];
    const int*   posE   = (const int*)d_in[1];
    const float* pe     = (const float*)d_in[2];
    const float* emb    = (const float*)d_in[3];
    const float* c1w    = (const float*)d_in[4];
    const float* c1b    = (const float*)d_in[5];
    const float* bn1g   = (const float*)d_in[6];
    const float* bn1b   = (const float*)d_in[7];
    const float* bn1m   = (const float*)d_in[8];
    const float* bn1v   = (const float*)d_in[9];
    const float* p1w    = (const float*)d_in[10];
    const float* cbw    = (const float*)d_in[11];
    const float* cbb    = (const float*)d_in[12];
    const float* gng    = (const float*)d_in[13];
    const float* gnb    = (const float*)d_in[14];
    const float* cbp    = (const float*)d_in[15];
    const float* d0w    = (const float*)d_in[16];
    const float* d0b    = (const float*)d_in[17];
    const float* d1w    = (const float*)d_in[18];
    const float* d1b    = (const float*)d_in[19];
    const float* bndg   = (const float*)d_in[20];
    const float* bndb   = (const float*)d_in[21];
    const float* bndm   = (const float*)d_in[22];
    const float* bndv   = (const float*)d_in[23];
    const float* pd     = (const float*)d_in[24];
    const float* finw   = (const float*)d_in[25];
    const float* finb   = (const float*)d_in[26];
    float* out = (float*)d_out;

    const int C1_SMEM = 15360 * 4;   // 61440 B
    const int CB_SMEM = 14208 * 4;   // 56832 B
    cudaFuncSetAttribute(conv1_tc, cudaFuncAttributeMaxDynamicSharedMemorySize, C1_SMEM);
    cudaFuncSetAttribute(cb_tc,    cudaFuncAttributeMaxDynamicSharedMemorySize, CB_SMEM);

    prep_w1h<<<(W_ * (K1P_ / 2) + 255) / 256, 256>>>(c1w);
    prep_cbwh<<<(CN_ * W_ * (W_ / 2) + 255) / 256, 256>>>(cbw);
    embed_h<<<(B_ * L_ * HPL_ + 255) / 256, 256>>>(x, pe, emb);

    {
        dim3 grid((Lp_ + 127) / 128, W_ / 128, B_);   // (4, 2, 128)
        conv1_tc<<<grid, 256, C1_SMEM>>>(c1b, bn1g, bn1b, bn1m, bn1v, p1w);
    }

    for (int i = 0; i < CN_; i++) {
        dim3 gridg(NB_ / 128, W_ / 128);              // (508, 2)
        cb_tc<<<gridg, 256, CB_SMEM>>>(i, cbb + i * W_);
        dim3 grids(G_, B_);
        gnstats_kernel<<<grids, 256>>>();
        int writeH = (i < CN_ - 1) ? 1 : 0;
        gnapply_kernel<<<((W_ / 2) * (NB_ / 4) + 255) / 256, 256>>>(
            gng + i * W_, gnb + i * W_, cbp + i, writeH);
    }

    {
        int warps = B_ * W_;
        int threads = warps * 32;
        maxfeat_kernel<<<(threads + 255) / 256, 256>>>(posE);
    }

    dense_kernel<<<B_, 256>>>(d0w, d0b, d1w, d1b, bndg, bndb, bndm, bndv,
                              pd, finw, finb, out);

    (void)in_sizes; (void)n_in; (void)out_size;
}